// round 3
// baseline (speedup 1.0000x reference)
#include <cuda_runtime.h>
#include <cuda_bf16.h>
#include <cstddef>

// Problem constants
#define BATCH   128
#define HW      50176          // 224*224
#define WIDTH   224
#define SEGS    196            // 14*14
#define NPOS    25088          // BATCH * SEGS
#define H_ELEMS 19267584ull    // 128*768*196
#define SL_ELEMS 6422528ull    // 128*224*224

// Scratch (device globals -- allocation is forbidden)
__device__ float g_actA[768 * NPOS];      // 77 MB
__device__ float g_actB[768 * NPOS];      // 77 MB
__device__ float g_stats[BATCH * SEGS * 9];
__device__ float g_alpha[2208];
__device__ float g_beta[2208];

// ---------------------------------------------------------------------------
// BN folding: alpha = g/sqrt(rv+eps); beta = (b-rm)*alpha + be
// ---------------------------------------------------------------------------
__global__ void prep_bn_kernel(const float* __restrict__ bias,
                               const float* __restrict__ g,
                               const float* __restrict__ be,
                               const float* __restrict__ rm,
                               const float* __restrict__ rv,
                               int co, int off) {
    int i = blockIdx.x * blockDim.x + threadIdx.x;
    if (i < co) {
        float a = g[i] / sqrtf(rv[i] + 1e-5f);
        g_alpha[off + i] = a;
        g_beta[off + i]  = (bias[i] - rm[i]) * a + be[i];
    }
}

// ---------------------------------------------------------------------------
// Segment accumulation: one block per batch image, smem atomics
// ---------------------------------------------------------------------------
__global__ void seg_accum_kernel(const float* __restrict__ x,
                                 const int* __restrict__ sliced) {
    __shared__ float acc[SEGS * 9];
    int b = blockIdx.x;
    for (int i = threadIdx.x; i < SEGS * 9; i += blockDim.x) acc[i] = 0.f;
    __syncthreads();

    const int*   sl = sliced + (size_t)b * HW;
    const float* xr = x + (size_t)b * 3 * HW;

    for (int p = threadIdx.x; p < HW; p += blockDim.x) {
        int id = sl[p];
        float r = (float)(p / WIDTH);
        float c = (float)(p % WIDTH);
        float v0 = xr[p];
        float v1 = xr[HW + p];
        float v2 = xr[2 * HW + p];
        float* a = &acc[id * 9];
        atomicAdd(a + 0, 1.0f);
        atomicAdd(a + 1, r);
        atomicAdd(a + 2, c);
        atomicAdd(a + 3, v0);
        atomicAdd(a + 4, v1);
        atomicAdd(a + 5, v2);
        atomicAdd(a + 6, v0 * v0);
        atomicAdd(a + 7, v1 * v1);
        atomicAdd(a + 8, v2 * v2);
    }
    __syncthreads();
    for (int i = threadIdx.x; i < SEGS * 9; i += blockDim.x)
        g_stats[(size_t)b * (SEGS * 9) + i] = acc[i];
}

// ---------------------------------------------------------------------------
// Finalize per-segment features -> g_actA rows 0..10, layout [11][NPOS]
// ---------------------------------------------------------------------------
__global__ void seg_finalize_kernel(const float* __restrict__ x) {
    int idx = blockIdx.x * blockDim.x + threadIdx.x;
    if (idx >= BATCH * SEGS) return;
    int b = idx / SEGS;

    const float* st = &g_stats[(size_t)idx * 9];
    float cnt  = st[0];
    float safe = fmaxf(cnt, 1.0f);
    float inv  = 1.0f / safe;
    float mrow = st[1] * inv;
    float mcol = st[2] * inv;
    float m0 = st[3] * inv, m1 = st[4] * inv, m2 = st[5] * inv;
    float dnm = 1.0f / fmaxf(cnt - 1.0f, 1.0f);
    float v0 = (st[6] - cnt * m0 * m0) * dnm;
    float v1 = (st[7] - cnt * m1 * m1) * dnm;
    float v2 = (st[8] - cnt * m2 * m2) * dnm;
    float s0 = (cnt > 1.0f) ? sqrtf(fmaxf(v0, 0.0f)) : 0.0f;
    float s1 = (cnt > 1.0f) ? sqrtf(fmaxf(v1, 0.0f)) : 0.0f;
    float s2 = (cnt > 1.0f) ? sqrtf(fmaxf(v2, 0.0f)) : 0.0f;

    int ri = min(max((int)mrow, 0), WIDTH - 1);
    int ci = min(max((int)mcol, 0), WIDTH - 1);
    const float* xr = x + (size_t)b * 3 * HW;
    int po = ri * WIDTH + ci;
    float gth0 = xr[po], gth1 = xr[HW + po], gth2 = xr[2 * HW + po];

    float mask = (cnt > 0.0f) ? 1.0f : 0.0f;
    float f[11] = {mrow, mcol, m0, m1, m2, s0, s1, s2, gth0, gth1, gth2};
#pragma unroll
    for (int c = 0; c < 11; c++)
        g_actA[(size_t)c * NPOS + idx] = f[c] * mask;
}

// ---------------------------------------------------------------------------
// SGEMM + BN(+ReLU): Y[m,n] = relu(alpha[m]*sum_k W[m,k]*X[k,n] + beta[m])
// BM=BN=64, BK=16, 256 threads, 4x4 microtiles. N = NPOS (multiple of 64).
// finalLayout: scatter to [B,768,196] (n = b*196+s)
// NOTE: W rows are only float4-loadable when K % 4 == 0 (layer 0 has K=11).
// ---------------------------------------------------------------------------
__global__ void sgemm_bn_kernel(const float* __restrict__ W,
                                const float* __restrict__ X,
                                float* __restrict__ Y,
                                int M, int K, int chanOff,
                                int doRelu, int finalLayout) {
    __shared__ float As[16][64];   // As[k][m] (transposed)
    __shared__ float Bs[16][64];   // Bs[k][n]
    const int N = NPOS;

    int tid = threadIdx.x;
    int bm = blockIdx.y * 64;
    int bn = blockIdx.x * 64;
    int ty = tid >> 4;          // 0..15
    int tx = tid & 15;          // 0..15

    int arow = tid >> 2;        // 0..63
    int acol = (tid & 3) * 4;   // 0,4,8,12
    int brow = tid >> 4;        // 0..15
    int bcol = (tid & 15) * 4;

    bool wVec = ((K & 3) == 0);   // rows of W 16B-aligned only if K % 4 == 0

    float acc[4][4] = {};

    for (int k0 = 0; k0 < K; k0 += 16) {
        // A tile (weights), transposed into smem
        float4 av = make_float4(0.f, 0.f, 0.f, 0.f);
        int gm = bm + arow;
        if (gm < M) {
            if (wVec && (k0 + acol + 3 < K)) {
                av = *(const float4*)&W[(size_t)gm * K + k0 + acol];
            } else {
                float t[4] = {0.f, 0.f, 0.f, 0.f};
#pragma unroll
                for (int u = 0; u < 4; u++)
                    if (k0 + acol + u < K) t[u] = W[(size_t)gm * K + k0 + acol + u];
                av = make_float4(t[0], t[1], t[2], t[3]);
            }
        }
        As[acol + 0][arow] = av.x;
        As[acol + 1][arow] = av.y;
        As[acol + 2][arow] = av.z;
        As[acol + 3][arow] = av.w;

        // B tile (activations): base is row-aligned (N mult of 4), always vec
        float4 bv = make_float4(0.f, 0.f, 0.f, 0.f);
        if (k0 + brow < K)
            bv = *(const float4*)&X[(size_t)(k0 + brow) * N + bn + bcol];
        *(float4*)&Bs[brow][bcol] = bv;

        __syncthreads();
#pragma unroll
        for (int k = 0; k < 16; k++) {
            float a[4], bb[4];
            *(float4*)a  = *(const float4*)&As[k][ty * 4];
            *(float4*)bb = *(const float4*)&Bs[k][tx * 4];
#pragma unroll
            for (int i = 0; i < 4; i++)
#pragma unroll
                for (int j = 0; j < 4; j++)
                    acc[i][j] += a[i] * bb[j];
        }
        __syncthreads();
    }

    // Epilogue
#pragma unroll
    for (int i = 0; i < 4; i++) {
        int m = bm + ty * 4 + i;
        if (m >= M) continue;
        float al = g_alpha[chanOff + m];
        float bt = g_beta[chanOff + m];
#pragma unroll
        for (int j = 0; j < 4; j++) {
            int n = bn + tx * 4 + j;
            float v = acc[i][j] * al + bt;
            if (doRelu) v = fmaxf(v, 0.0f);
            if (!finalLayout) {
                Y[(size_t)m * N + n] = v;
            } else {
                int b = n / SEGS;
                int s = n - b * SEGS;
                Y[((size_t)b * 768 + m) * SEGS + s] = v;
            }
        }
    }
}

// ---------------------------------------------------------------------------
// sliced (int32) -> float copy into front of output
// ---------------------------------------------------------------------------
__global__ void copy_sliced_kernel(const int* __restrict__ sl,
                                   float* __restrict__ out, int n4) {
    int i = blockIdx.x * blockDim.x + threadIdx.x;
    if (i < n4) {
        int4 v = ((const int4*)sl)[i];
        ((float4*)out)[i] = make_float4((float)v.x, (float)v.y, (float)v.z, (float)v.w);
    }
}

// ---------------------------------------------------------------------------
extern "C" void kernel_launch(void* const* d_in, const int* in_sizes, int n_in,
                              void* d_out, int out_size) {
    const float* x      = (const float*)d_in[0];
    const int*   sliced = (const int*)d_in[1];

    float* actA;
    float* actB;
    cudaGetSymbolAddress((void**)&actA, g_actA);
    cudaGetSymbolAddress((void**)&actB, g_actB);

    float* out_f = (float*)d_out;
    // Output is flattened tuple (sliced, h). Hedge on out_size.
    size_t front = ((size_t)out_size > H_ELEMS) ? ((size_t)out_size - H_ELEMS) : 0;
    float* h_out = out_f + front;

    if (front > 0) {
        int n4 = (int)(front / 4);
        copy_sliced_kernel<<<(n4 + 255) / 256, 256>>>(sliced, out_f, n4);
    }

    // BN prep (5 layers)
    static const int COS[5]  = {96, 192, 384, 768, 768};
    static const int OFFS[5] = {0, 96, 288, 672, 1440};
    for (int i = 0; i < 5; i++) {
        const float* bb = (const float*)d_in[2 + 6 * i + 1];
        const float* gg = (const float*)d_in[2 + 6 * i + 2];
        const float* be = (const float*)d_in[2 + 6 * i + 3];
        const float* rm = (const float*)d_in[2 + 6 * i + 4];
        const float* rv = (const float*)d_in[2 + 6 * i + 5];
        prep_bn_kernel<<<(COS[i] + 255) / 256, 256>>>(bb, gg, be, rm, rv, COS[i], OFFS[i]);
    }

    // Segment features
    seg_accum_kernel<<<BATCH, 512>>>(x, sliced);
    seg_finalize_kernel<<<(BATCH * SEGS + 255) / 256, 256>>>(x);

    // MLP chain (ping-pong actA/actB)
    const float* w0 = (const float*)d_in[2 + 0 * 6];
    const float* w1 = (const float*)d_in[2 + 1 * 6];
    const float* w2 = (const float*)d_in[2 + 2 * 6];
    const float* w3 = (const float*)d_in[2 + 3 * 6];
    const float* w4 = (const float*)d_in[2 + 4 * 6];

    dim3 blk(256);
    // L0: 11 -> 96, A -> B, relu
    sgemm_bn_kernel<<<dim3(NPOS / 64, (96 + 63) / 64), blk>>>(w0, actA, actB, 96, 11, 0, 1, 0);
    // L1: 96 -> 192, B -> A, relu
    sgemm_bn_kernel<<<dim3(NPOS / 64, 192 / 64), blk>>>(w1, actB, actA, 192, 96, 96, 1, 0);
    // L2: 192 -> 384, A -> B, relu
    sgemm_bn_kernel<<<dim3(NPOS / 64, 384 / 64), blk>>>(w2, actA, actB, 384, 192, 288, 1, 0);
    // L3: 384 -> 768, B -> A, relu
    sgemm_bn_kernel<<<dim3(NPOS / 64, 768 / 64), blk>>>(w3, actB, actA, 768, 384, 672, 1, 0);
    // L4: 768 -> 768, A -> out, no relu, final layout
    sgemm_bn_kernel<<<dim3(NPOS / 64, 768 / 64), blk>>>(w4, actA, h_out, 768, 768, 1440, 0, 1);
}

// round 11
// speedup vs baseline: 1.9404x; 1.9404x over previous
#include <cuda_runtime.h>
#include <cuda_bf16.h>
#include <cstdint>
#include <cstddef>

// ---------------------------------------------------------------------------
// Problem constants
// ---------------------------------------------------------------------------
#define BATCH   128
#define HW      50176          // 224*224
#define WIDTH   224
#define SEGS    196            // 14*14
#define NPOS    25088          // BATCH * SEGS
#define H_ELEMS 19267584ull    // 128*768*196

typedef __nv_bfloat16 bf16;

// ---------------------------------------------------------------------------
// Device-global scratch (allocation forbidden)
// ---------------------------------------------------------------------------
__device__ bf16 g_bufA_hi[(size_t)NPOS * 768];
__device__ bf16 g_bufA_lo[(size_t)NPOS * 768];
__device__ bf16 g_bufB_hi[(size_t)NPOS * 768];
__device__ bf16 g_bufB_lo[(size_t)NPOS * 768];
__device__ bf16 g_wHi[768 * 768];
__device__ bf16 g_wLo[768 * 768];
__device__ float g_stats2[(size_t)NPOS * 12];
__device__ float g_feat[(size_t)NPOS * 16];
__device__ float g_alpha[2208];
__device__ float g_beta[2208];

// ---------------------------------------------------------------------------
// Helpers (baseline PTX only -- NO tcgen05/TMEM; harness targets sm_103 plain)
// ---------------------------------------------------------------------------
__device__ __forceinline__ uint32_t smem_to_u32(const void* smem_ptr) {
    uint32_t addr;
    asm("{ .reg .u64 tmp; cvta.to.shared.u64 tmp, %1; cvt.u32.u64 %0, tmp; }"
        : "=r"(addr) : "l"(smem_ptr));
    return addr;
}

__device__ __forceinline__ void cpasync16(uint32_t saddr, const void* gaddr) {
    asm volatile("cp.async.ca.shared.global [%0], [%1], 16;"
                 :: "r"(saddr), "l"(gaddr) : "memory");
}

__device__ __forceinline__ void mma16816(float* d, const uint32_t* a,
                                         const uint32_t* b) {
    asm volatile(
        "mma.sync.aligned.m16n8k16.row.col.f32.bf16.bf16.f32 "
        "{%0,%1,%2,%3}, {%4,%5,%6,%7}, {%8,%9}, {%0,%1,%2,%3};"
        : "+f"(d[0]), "+f"(d[1]), "+f"(d[2]), "+f"(d[3])
        : "r"(a[0]), "r"(a[1]), "r"(a[2]), "r"(a[3]), "r"(b[0]), "r"(b[1]));
}

__device__ __forceinline__ uint32_t lds32(uint32_t addr) {
    uint32_t v;
    asm volatile("ld.shared.b32 %0, [%1];" : "=r"(v) : "r"(addr));
    return v;
}

// ---------------------------------------------------------------------------
// BN folding
// ---------------------------------------------------------------------------
__global__ void prep_bn_kernel(const float* __restrict__ bias,
                               const float* __restrict__ g,
                               const float* __restrict__ be,
                               const float* __restrict__ rm,
                               const float* __restrict__ rv,
                               int co, int off) {
    int i = blockIdx.x * blockDim.x + threadIdx.x;
    if (i < co) {
        float a = g[i] / sqrtf(rv[i] + 1e-5f);
        g_alpha[off + i] = a;
        g_beta[off + i]  = (bias[i] - rm[i]) * a + be[i];
    }
}

// ---------------------------------------------------------------------------
// Weight prep: fp32 -> (hi, lo) bf16 split, zero-padded to [COpad][Kpad]
// ---------------------------------------------------------------------------
__global__ void prep_w_kernel(const float* __restrict__ W,
                              int CO, int K, int COpad, int Kpad) {
    int i = blockIdx.x * blockDim.x + threadIdx.x;
    if (i >= COpad * Kpad) return;
    int co = i / Kpad;
    int k  = i - co * Kpad;
    float v = (co < CO && k < K) ? W[co * K + k] : 0.0f;
    bf16 h = __float2bfloat16(v);
    g_wHi[i] = h;
    g_wLo[i] = __float2bfloat16(v - __bfloat162float(h));
}

// ---------------------------------------------------------------------------
// Zero the stats accumulator
// ---------------------------------------------------------------------------
__global__ void zero_stats_kernel() {
    int i = blockIdx.x * blockDim.x + threadIdx.x;
    int n4 = NPOS * 12 / 4;
    if (i < n4) ((float4*)g_stats2)[i] = make_float4(0.f, 0.f, 0.f, 0.f);
}

// ---------------------------------------------------------------------------
// Segment accumulation via global vector reductions
// ---------------------------------------------------------------------------
__device__ __forceinline__ void red4(float* p, float a, float b, float c, float d) {
    asm volatile("red.global.add.v4.f32 [%0], {%1, %2, %3, %4};"
                 :: "l"(__cvta_generic_to_global(p)),
                    "f"(a), "f"(b), "f"(c), "f"(d) : "memory");
}

__global__ void seg_accum_kernel(const float* __restrict__ x,
                                 const int* __restrict__ sliced) {
    int t = blockIdx.x * blockDim.x + threadIdx.x;
    if (t >= BATCH * HW / 4) return;
    int g = t * 4;
    int b = g / HW;
    int p = g - b * HW;

    int4 id4 = *(const int4*)&sliced[g];
    const float* xr = x + (size_t)b * 3 * HW;
    float4 c0 = *(const float4*)&xr[p];
    float4 c1 = *(const float4*)&xr[HW + p];
    float4 c2 = *(const float4*)&xr[2 * HW + p];

    float r = (float)(p / WIDTH);
    float cb = (float)(p % WIDTH);

    int   ids[4] = {id4.x, id4.y, id4.z, id4.w};
    float a0[4] = {c0.x, c0.y, c0.z, c0.w};
    float a1[4] = {c1.x, c1.y, c1.z, c1.w};
    float a2[4] = {c2.x, c2.y, c2.z, c2.w};

#pragma unroll
    for (int u = 0; u < 4; u++) {
        float* base = &g_stats2[((size_t)b * SEGS + ids[u]) * 12];
        red4(base,     1.0f, r, cb + (float)u, a0[u]);
        red4(base + 4, a1[u], a2[u], a0[u] * a0[u], a1[u] * a1[u]);
        atomicAdd(base + 8, a2[u] * a2[u]);
    }
}

// ---------------------------------------------------------------------------
// Finalize segment features -> g_feat [pos][16] (11 valid)
// ---------------------------------------------------------------------------
__global__ void seg_finalize_kernel(const float* __restrict__ x) {
    int idx = blockIdx.x * blockDim.x + threadIdx.x;
    if (idx >= NPOS) return;
    int b = idx / SEGS;

    const float* st = &g_stats2[(size_t)idx * 12];
    float cnt  = st[0];
    float inv  = 1.0f / fmaxf(cnt, 1.0f);
    float mrow = st[1] * inv;
    float mcol = st[2] * inv;
    float m0 = st[3] * inv, m1 = st[4] * inv, m2 = st[5] * inv;
    float dnm = 1.0f / fmaxf(cnt - 1.0f, 1.0f);
    float v0 = (st[6] - cnt * m0 * m0) * dnm;
    float v1 = (st[7] - cnt * m1 * m1) * dnm;
    float v2 = (st[8] - cnt * m2 * m2) * dnm;
    float s0 = (cnt > 1.0f) ? sqrtf(fmaxf(v0, 0.0f)) : 0.0f;
    float s1 = (cnt > 1.0f) ? sqrtf(fmaxf(v1, 0.0f)) : 0.0f;
    float s2 = (cnt > 1.0f) ? sqrtf(fmaxf(v2, 0.0f)) : 0.0f;

    int ri = min(max((int)mrow, 0), WIDTH - 1);
    int ci = min(max((int)mcol, 0), WIDTH - 1);
    const float* xr = x + (size_t)b * 3 * HW;
    int po = ri * WIDTH + ci;
    float gth0 = xr[po], gth1 = xr[HW + po], gth2 = xr[2 * HW + po];

    float mask = (cnt > 0.0f) ? 1.0f : 0.0f;
    float f[11] = {mrow, mcol, m0, m1, m2, s0, s1, s2, gth0, gth1, gth2};
#pragma unroll
    for (int c = 0; c < 11; c++)
        g_feat[(size_t)idx * 16 + c] = f[c] * mask;
}

// ---------------------------------------------------------------------------
// Layer 0 (K=11, CO=96): direct -> bufA split bf16, stride 128, zero pad
// ---------------------------------------------------------------------------
__global__ void l0_kernel(const float* __restrict__ w0) {
    __shared__ float f[11];
    int pos = blockIdx.x;
    int co = threadIdx.x;   // 0..127
    if (co < 11) f[co] = g_feat[(size_t)pos * 16 + co];
    __syncthreads();

    bf16 h = __float2bfloat16(0.0f);
    bf16 l = h;
    if (co < 96) {
        float v = 0.0f;
#pragma unroll
        for (int k = 0; k < 11; k++) v += __ldg(&w0[co * 11 + k]) * f[k];
        v = fmaxf(v * g_alpha[co] + g_beta[co], 0.0f);
        h = __float2bfloat16(v);
        l = __float2bfloat16(v - __bfloat162float(h));
    }
    g_bufA_hi[(size_t)pos * 128 + co] = h;
    g_bufA_lo[(size_t)pos * 128 + co] = l;
}

// ---------------------------------------------------------------------------
// Split-bf16 HMMA GEMM + BN(+ReLU)
//   D[m,n] = sum_k W[m,k]*X[n,k], W/X each split hi+lo (3 mma per frag pair)
//   CTA tile 128x128, BK=32, 256 threads = 8 warps (2 M x 4 N), warp 64x32.
//   cp.async double buffered. fp32 accum in registers.
// ---------------------------------------------------------------------------
#define PITCH 80                       // bytes per smem row: 32 bf16 + 8 pad
#define SBUF  (128 * PITCH)            // one tile buffer: 10240 B
#define STAGE (4 * SBUF)               // AH, AL, BH, BL
#define GSMEM (2 * STAGE)              // 81920 B

__device__ __forceinline__ void load_stage(
    uint32_t sb, int st, int k0, int m0, int n0, int Kpad, int strideIn,
    const bf16* __restrict__ Xhi, const bf16* __restrict__ Xlo, int tid) {
#pragma unroll
    for (int i = 0; i < 2; i++) {
        int lin = i * 256 + tid;
        int row = lin >> 2;
        int kc  = lin & 3;
        uint32_t soff = (uint32_t)(st * STAGE + row * PITCH + kc * 16);
        size_t aoff = (size_t)(m0 + row) * Kpad + k0 + kc * 8;
        size_t boff = (size_t)(n0 + row) * strideIn + k0 + kc * 8;
        cpasync16(sb + soff,            &g_wHi[aoff]);
        cpasync16(sb + SBUF + soff,     &g_wLo[aoff]);
        cpasync16(sb + 2 * SBUF + soff, &Xhi[boff]);
        cpasync16(sb + 3 * SBUF + soff, &Xlo[boff]);
    }
    asm volatile("cp.async.commit_group;" ::: "memory");
}

__global__ void __launch_bounds__(256, 1)
gemm_mma_kernel(const bf16* __restrict__ Xhi, const bf16* __restrict__ Xlo,
                int strideIn, int Kpad, int CO, int chanOff, int doRelu,
                bf16* __restrict__ Yhi, bf16* __restrict__ Ylo, int strideOut,
                float* __restrict__ Yfinal) {
    extern __shared__ char smem[];
    uint32_t sb = smem_to_u32(smem);

    int tid = threadIdx.x;
    int wid = tid >> 5;
    int lane = tid & 31;
    int g = lane >> 2;
    int tg = lane & 3;
    int m0 = blockIdx.y * 128;
    int n0 = blockIdx.x * 128;
    int wm = (wid & 1) * 64;
    int wn = (wid >> 1) * 32;

    float d[4][4][4];
#pragma unroll
    for (int mi = 0; mi < 4; mi++)
#pragma unroll
        for (int ni = 0; ni < 4; ni++)
#pragma unroll
            for (int r = 0; r < 4; r++) d[mi][ni][r] = 0.0f;

    int nCh = Kpad >> 5;

    load_stage(sb, 0, 0, m0, n0, Kpad, strideIn, Xhi, Xlo, tid);

    for (int ch = 0; ch < nCh; ch++) {
        if (ch + 1 < nCh) {
            load_stage(sb, (ch + 1) & 1, (ch + 1) << 5, m0, n0, Kpad,
                       strideIn, Xhi, Xlo, tid);
            asm volatile("cp.async.wait_group 1;" ::: "memory");
        } else {
            asm volatile("cp.async.wait_group 0;" ::: "memory");
        }
        __syncthreads();

        uint32_t base = sb + (uint32_t)((ch & 1) * STAGE);
#pragma unroll
        for (int ks = 0; ks < 2; ks++) {
            uint32_t c0 = (uint32_t)(ks * 32 + tg * 4);  // byte col offset

            uint32_t ah[4][4], al[4][4];
#pragma unroll
            for (int mi = 0; mi < 4; mi++) {
                uint32_t a0 = base + (uint32_t)((wm + mi * 16 + g) * PITCH) + c0;
                ah[mi][0] = lds32(a0);
                ah[mi][1] = lds32(a0 + 8 * PITCH);
                ah[mi][2] = lds32(a0 + 16);
                ah[mi][3] = lds32(a0 + 8 * PITCH + 16);
                uint32_t a1 = a0 + SBUF;
                al[mi][0] = lds32(a1);
                al[mi][1] = lds32(a1 + 8 * PITCH);
                al[mi][2] = lds32(a1 + 16);
                al[mi][3] = lds32(a1 + 8 * PITCH + 16);
            }
            uint32_t bh[4][2], bl[4][2];
#pragma unroll
            for (int ni = 0; ni < 4; ni++) {
                uint32_t b0 = base + 2 * SBUF +
                              (uint32_t)((wn + ni * 8 + g) * PITCH) + c0;
                bh[ni][0] = lds32(b0);
                bh[ni][1] = lds32(b0 + 16);
                bl[ni][0] = lds32(b0 + SBUF);
                bl[ni][1] = lds32(b0 + SBUF + 16);
            }
#pragma unroll
            for (int mi = 0; mi < 4; mi++)
#pragma unroll
                for (int ni = 0; ni < 4; ni++) {
                    mma16816(d[mi][ni], ah[mi], bh[ni]);
                    mma16816(d[mi][ni], ah[mi], bl[ni]);
                    mma16816(d[mi][ni], al[mi], bh[ni]);
                }
        }
        __syncthreads();
    }

    // Epilogue: thread owns (m = wm+mi*16+g(+8), n = wn+ni*8+tg*2(+1))
#pragma unroll
    for (int mi = 0; mi < 4; mi++) {
#pragma unroll
        for (int r2 = 0; r2 < 2; r2++) {
            int m = m0 + wm + mi * 16 + g + r2 * 8;
            if (m >= CO) continue;
            float al_ = g_alpha[chanOff + m];
            float bt_ = g_beta[chanOff + m];
#pragma unroll
            for (int ni = 0; ni < 4; ni++) {
#pragma unroll
                for (int c = 0; c < 2; c++) {
                    int n = n0 + wn + ni * 8 + tg * 2 + c;
                    float v = d[mi][ni][r2 * 2 + c] * al_ + bt_;
                    if (doRelu) v = fmaxf(v, 0.0f);
                    if (Yfinal == nullptr) {
                        bf16 h = __float2bfloat16(v);
                        size_t o = (size_t)n * strideOut + m;
                        Yhi[o] = h;
                        Ylo[o] = __float2bfloat16(v - __bfloat162float(h));
                    } else {
                        int b = n / SEGS;
                        int s = n - b * SEGS;
                        Yfinal[((size_t)b * 768 + m) * SEGS + s] = v;
                    }
                }
            }
        }
    }
}

// ---------------------------------------------------------------------------
// sliced (int32) -> float copy into front of output
// ---------------------------------------------------------------------------
__global__ void copy_sliced_kernel(const int* __restrict__ sl,
                                   float* __restrict__ out, int n4) {
    int i = blockIdx.x * blockDim.x + threadIdx.x;
    if (i < n4) {
        int4 v = ((const int4*)sl)[i];
        ((float4*)out)[i] = make_float4((float)v.x, (float)v.y, (float)v.z, (float)v.w);
    }
}

// ---------------------------------------------------------------------------
extern "C" void kernel_launch(void* const* d_in, const int* in_sizes, int n_in,
                              void* d_out, int out_size) {
    const float* x      = (const float*)d_in[0];
    const int*   sliced = (const int*)d_in[1];

    bf16 *bufA_hi, *bufA_lo, *bufB_hi, *bufB_lo;
    cudaGetSymbolAddress((void**)&bufA_hi, g_bufA_hi);
    cudaGetSymbolAddress((void**)&bufA_lo, g_bufA_lo);
    cudaGetSymbolAddress((void**)&bufB_hi, g_bufB_hi);
    cudaGetSymbolAddress((void**)&bufB_lo, g_bufB_lo);

    cudaFuncSetAttribute(gemm_mma_kernel,
                         cudaFuncAttributeMaxDynamicSharedMemorySize, GSMEM);

    float* out_f = (float*)d_out;
    size_t front = ((size_t)out_size > H_ELEMS) ? ((size_t)out_size - H_ELEMS) : 0;
    float* h_out = out_f + front;

    if (front > 0) {
        int n4 = (int)(front / 4);
        copy_sliced_kernel<<<(n4 + 255) / 256, 256>>>(sliced, out_f, n4);
    }

    // BN prep
    static const int COS[5]  = {96, 192, 384, 768, 768};
    static const int OFFS[5] = {0, 96, 288, 672, 1440};
    for (int i = 0; i < 5; i++) {
        const float* bb = (const float*)d_in[2 + 6 * i + 1];
        const float* gg = (const float*)d_in[2 + 6 * i + 2];
        const float* be = (const float*)d_in[2 + 6 * i + 3];
        const float* rm = (const float*)d_in[2 + 6 * i + 4];
        const float* rv = (const float*)d_in[2 + 6 * i + 5];
        prep_bn_kernel<<<(COS[i] + 255) / 256, 256>>>(bb, gg, be, rm, rv, COS[i], OFFS[i]);
    }

    // Segment features
    zero_stats_kernel<<<(NPOS * 12 / 4 + 255) / 256, 256>>>();
    seg_accum_kernel<<<(BATCH * HW / 4 + 255) / 256, 256>>>(x, sliced);
    seg_finalize_kernel<<<(NPOS + 255) / 256, 256>>>(x);

    const float* w0 = (const float*)d_in[2 + 0 * 6];
    const float* w1 = (const float*)d_in[2 + 1 * 6];
    const float* w2 = (const float*)d_in[2 + 2 * 6];
    const float* w3 = (const float*)d_in[2 + 3 * 6];
    const float* w4 = (const float*)d_in[2 + 4 * 6];

    // L0: 11 -> 96 (direct), writes bufA (stride 128, padded)
    l0_kernel<<<NPOS, 128>>>(w0);

    // L1: K=96 (stride 128 input) -> 192: bufA -> bufB
    prep_w_kernel<<<(256 * 96 + 255) / 256, 256>>>(w1, 192, 96, 256, 96);
    gemm_mma_kernel<<<dim3(NPOS / 128, 2), 256, GSMEM>>>(
        bufA_hi, bufA_lo, 128, 96, 192, 96, 1, bufB_hi, bufB_lo, 192, nullptr);

    // L2: 192 -> 384: bufB -> bufA
    prep_w_kernel<<<(384 * 192 + 255) / 256, 256>>>(w2, 384, 192, 384, 192);
    gemm_mma_kernel<<<dim3(NPOS / 128, 3), 256, GSMEM>>>(
        bufB_hi, bufB_lo, 192, 192, 384, 288, 1, bufA_hi, bufA_lo, 384, nullptr);

    // L3: 384 -> 768: bufA -> bufB
    prep_w_kernel<<<(768 * 384 + 255) / 256, 256>>>(w3, 768, 384, 768, 384);
    gemm_mma_kernel<<<dim3(NPOS / 128, 6), 256, GSMEM>>>(
        bufA_hi, bufA_lo, 384, 384, 768, 672, 1, bufB_hi, bufB_lo, 768, nullptr);

    // L4: 768 -> 768: bufB -> final fp32 output [B][768][196]
    prep_w_kernel<<<(768 * 768 + 255) / 256, 256>>>(w4, 768, 768, 768, 768);
    gemm_mma_kernel<<<dim3(NPOS / 128, 6), 256, GSMEM>>>(
        bufB_hi, bufB_lo, 768, 768, 768, 1440, 0, nullptr, nullptr, 0, h_out);
}

// round 13
// speedup vs baseline: 2.2751x; 1.1725x over previous
#include <cuda_runtime.h>
#include <cuda_bf16.h>
#include <cstdint>
#include <cstddef>

// ---------------------------------------------------------------------------
// Problem constants
// ---------------------------------------------------------------------------
#define BATCH   128
#define HW      50176          // 224*224
#define WIDTH   224
#define SEGS    196            // 14*14
#define NPOS    25088          // BATCH * SEGS
#define H_ELEMS 19267584ull    // 128*768*196

typedef __nv_bfloat16 bf16;

// Weight arena: padded per-layer regions (rows padded to M-tile, K padded to 64)
// L1: 256x128 @0, L2: 384x192 @32768, L3: 768x384 @106496, L4: 768x768 @401408
#define WOFF1 0
#define WOFF2 32768
#define WOFF3 106496
#define WOFF4 401408
#define WTOT  991232

// ---------------------------------------------------------------------------
// Device-global scratch (allocation forbidden)
// ---------------------------------------------------------------------------
__device__ bf16 g_bufA_hi[(size_t)NPOS * 768];
__device__ bf16 g_bufA_lo[(size_t)NPOS * 768];
__device__ bf16 g_bufB_hi[(size_t)NPOS * 768];
__device__ bf16 g_bufB_lo[(size_t)NPOS * 768];
__device__ bf16 g_wHi[WTOT];
__device__ bf16 g_wLo[WTOT];
__device__ float g_stats2[(size_t)NPOS * 12];
__device__ float g_alpha[2208];
__device__ float g_beta[2208];

// ---------------------------------------------------------------------------
// Helpers (baseline PTX only -- NO tcgen05/TMEM; toolchain targets sm_103 plain)
// ---------------------------------------------------------------------------
__device__ __forceinline__ uint32_t smem_to_u32(const void* smem_ptr) {
    uint32_t addr;
    asm("{ .reg .u64 tmp; cvta.to.shared.u64 tmp, %1; cvt.u32.u64 %0, tmp; }"
        : "=r"(addr) : "l"(smem_ptr));
    return addr;
}

__device__ __forceinline__ void cpasync16(uint32_t saddr, const void* gaddr) {
    asm volatile("cp.async.ca.shared.global [%0], [%1], 16;"
                 :: "r"(saddr), "l"(gaddr) : "memory");
}

__device__ __forceinline__ void mma16816(float* d, const uint32_t* a,
                                         const uint32_t* b) {
    asm volatile(
        "mma.sync.aligned.m16n8k16.row.col.f32.bf16.bf16.f32 "
        "{%0,%1,%2,%3}, {%4,%5,%6,%7}, {%8,%9}, {%0,%1,%2,%3};"
        : "+f"(d[0]), "+f"(d[1]), "+f"(d[2]), "+f"(d[3])
        : "r"(a[0]), "r"(a[1]), "r"(a[2]), "r"(a[3]), "r"(b[0]), "r"(b[1]));
}

__device__ __forceinline__ void ldmx4(uint32_t* r, uint32_t addr) {
    asm volatile(
        "ldmatrix.sync.aligned.m8n8.x4.shared.b16 {%0,%1,%2,%3}, [%4];"
        : "=r"(r[0]), "=r"(r[1]), "=r"(r[2]), "=r"(r[3]) : "r"(addr));
}

// ---------------------------------------------------------------------------
// BN folding: all 5 layers in one launch
// ---------------------------------------------------------------------------
struct BNArgs { const float* p[25]; };   // per layer: b, g, be, rm, rv

__global__ void prep_bn_all_kernel(BNArgs a) {
    int i = blockIdx.x * blockDim.x + threadIdx.x;
    if (i >= 2208) return;
    const int cos[5]  = {96, 192, 384, 768, 768};
    const int offs[5] = {0, 96, 288, 672, 1440};
    int l = 0;
    while (l < 4 && i >= offs[l + 1]) l++;
    int c = i - offs[l];
    if (c >= cos[l]) return;
    const float* bb = a.p[l * 5 + 0];
    const float* gg = a.p[l * 5 + 1];
    const float* be = a.p[l * 5 + 2];
    const float* rm = a.p[l * 5 + 3];
    const float* rv = a.p[l * 5 + 4];
    float al = gg[c] / sqrtf(rv[c] + 1e-5f);
    g_alpha[i] = al;
    g_beta[i]  = (bb[c] - rm[c]) * al + be[c];
}

// ---------------------------------------------------------------------------
// Weight prep: all 4 GEMM layers, fp32 -> (hi, lo) bf16, zero-padded arena
// ---------------------------------------------------------------------------
struct WArgs { const float* w[4]; };     // w1..w4

__global__ void prep_w_all_kernel(WArgs a) {
    int i = blockIdx.x * blockDim.x + threadIdx.x;
    if (i >= WTOT) return;
    const int segB[5] = {0, WOFF2, WOFF3, WOFF4, WTOT};
    const int CO[4]   = {192, 384, 768, 768};
    const int K[4]    = {96, 192, 384, 768};
    const int KP[4]   = {128, 192, 384, 768};
    int l = 0;
    while (l < 3 && i >= segB[l + 1]) l++;
    int loc = i - segB[l];
    int co = loc / KP[l];
    int k  = loc - co * KP[l];
    float v = (co < CO[l] && k < K[l]) ? a.w[l][co * K[l] + k] : 0.0f;
    bf16 h = __float2bfloat16(v);
    g_wHi[i] = h;
    g_wLo[i] = __float2bfloat16(v - __bfloat162float(h));
}

// ---------------------------------------------------------------------------
// Zero the stats accumulator
// ---------------------------------------------------------------------------
__global__ void zero_stats_kernel() {
    int i = blockIdx.x * blockDim.x + threadIdx.x;
    int n4 = NPOS * 12 / 4;
    if (i < n4) ((float4*)g_stats2)[i] = make_float4(0.f, 0.f, 0.f, 0.f);
}

// ---------------------------------------------------------------------------
// Segment accumulation via global vector reductions
// ---------------------------------------------------------------------------
__device__ __forceinline__ void red4(float* p, float a, float b, float c, float d) {
    asm volatile("red.global.add.v4.f32 [%0], {%1, %2, %3, %4};"
                 :: "l"(__cvta_generic_to_global(p)),
                    "f"(a), "f"(b), "f"(c), "f"(d) : "memory");
}

__global__ void seg_accum_kernel(const float* __restrict__ x,
                                 const int* __restrict__ sliced) {
    int t = blockIdx.x * blockDim.x + threadIdx.x;
    if (t >= BATCH * HW / 4) return;
    int g = t * 4;
    int b = g / HW;
    int p = g - b * HW;

    int4 id4 = *(const int4*)&sliced[g];
    const float* xr = x + (size_t)b * 3 * HW;
    float4 c0 = *(const float4*)&xr[p];
    float4 c1 = *(const float4*)&xr[HW + p];
    float4 c2 = *(const float4*)&xr[2 * HW + p];

    float r = (float)(p / WIDTH);
    float cb = (float)(p % WIDTH);

    int   ids[4] = {id4.x, id4.y, id4.z, id4.w};
    float a0[4] = {c0.x, c0.y, c0.z, c0.w};
    float a1[4] = {c1.x, c1.y, c1.z, c1.w};
    float a2[4] = {c2.x, c2.y, c2.z, c2.w};

#pragma unroll
    for (int u = 0; u < 4; u++) {
        float* base = &g_stats2[((size_t)b * SEGS + ids[u]) * 12];
        red4(base,     1.0f, r, cb + (float)u, a0[u]);
        red4(base + 4, a1[u], a2[u], a0[u] * a0[u], a1[u] * a1[u]);
        atomicAdd(base + 8, a2[u] * a2[u]);
    }
}

// ---------------------------------------------------------------------------
// Layer 0 fused with finalize: per pos, compute features from stats, then
// 11 -> 96 dot products + BN + ReLU -> bufA split bf16 (stride 128, zero pad)
// ---------------------------------------------------------------------------
__global__ void l0_kernel(const float* __restrict__ x,
                          const float* __restrict__ w0) {
    __shared__ float f[11];
    int pos = blockIdx.x;
    int co = threadIdx.x;   // 0..127

    if (co == 0) {
        int b = pos / SEGS;
        const float* st = &g_stats2[(size_t)pos * 12];
        float cnt  = st[0];
        float inv  = 1.0f / fmaxf(cnt, 1.0f);
        float mrow = st[1] * inv;
        float mcol = st[2] * inv;
        float m0 = st[3] * inv, m1 = st[4] * inv, m2 = st[5] * inv;
        float dnm = 1.0f / fmaxf(cnt - 1.0f, 1.0f);
        float v0 = (st[6] - cnt * m0 * m0) * dnm;
        float v1 = (st[7] - cnt * m1 * m1) * dnm;
        float v2 = (st[8] - cnt * m2 * m2) * dnm;
        float s0 = (cnt > 1.0f) ? sqrtf(fmaxf(v0, 0.0f)) : 0.0f;
        float s1 = (cnt > 1.0f) ? sqrtf(fmaxf(v1, 0.0f)) : 0.0f;
        float s2 = (cnt > 1.0f) ? sqrtf(fmaxf(v2, 0.0f)) : 0.0f;
        int ri = min(max((int)mrow, 0), WIDTH - 1);
        int ci = min(max((int)mcol, 0), WIDTH - 1);
        const float* xr = x + (size_t)b * 3 * HW;
        int po = ri * WIDTH + ci;
        float mask = (cnt > 0.0f) ? 1.0f : 0.0f;
        f[0] = mrow * mask;  f[1] = mcol * mask;
        f[2] = m0 * mask;    f[3] = m1 * mask;    f[4] = m2 * mask;
        f[5] = s0 * mask;    f[6] = s1 * mask;    f[7] = s2 * mask;
        f[8] = xr[po] * mask; f[9] = xr[HW + po] * mask; f[10] = xr[2 * HW + po] * mask;
    }
    __syncthreads();

    bf16 h = __float2bfloat16(0.0f);
    bf16 l = h;
    if (co < 96) {
        float v = 0.0f;
#pragma unroll
        for (int k = 0; k < 11; k++) v += __ldg(&w0[co * 11 + k]) * f[k];
        v = fmaxf(v * g_alpha[co] + g_beta[co], 0.0f);
        h = __float2bfloat16(v);
        l = __float2bfloat16(v - __bfloat162float(h));
    }
    g_bufA_hi[(size_t)pos * 128 + co] = h;
    g_bufA_lo[(size_t)pos * 128 + co] = l;
}

// ---------------------------------------------------------------------------
// Split-bf16 HMMA GEMM + BN(+ReLU), ldmatrix fragments, BK=64, double buffer
//   D[m,n] = sum_k W[m,k]*X[n,k]; 3 mma per frag pair (hh + hl + lh)
//   CTA 128x128, 256 threads = 8 warps (2 M x 4 N), warp tile 64x32
// ---------------------------------------------------------------------------
#define PITCH 144                      // bytes/row: 64 bf16 = 128 B + 16 pad
#define SBUF  (128 * PITCH)            // 18432 B per tile
#define STAGE (4 * SBUF)               // AH, AL, BH, BL = 73728 B
#define GSMEM (2 * STAGE)              // 147456 B

__device__ __forceinline__ void load_stage(
    uint32_t sb, int st, int k0, int m0, int n0, int Kpad, int strideIn,
    const bf16* __restrict__ Whi, const bf16* __restrict__ Wlo,
    const bf16* __restrict__ Xhi, const bf16* __restrict__ Xlo, int tid) {
#pragma unroll
    for (int i = 0; i < 4; i++) {
        int lin = i * 256 + tid;       // 0..1023
        int row = lin >> 3;
        int kc  = lin & 7;
        uint32_t soff = (uint32_t)(st * STAGE + row * PITCH + kc * 16);
        size_t aoff = (size_t)(m0 + row) * Kpad + k0 + kc * 8;
        size_t boff = (size_t)(n0 + row) * strideIn + k0 + kc * 8;
        cpasync16(sb + soff,            &Whi[aoff]);
        cpasync16(sb + SBUF + soff,     &Wlo[aoff]);
        cpasync16(sb + 2 * SBUF + soff, &Xhi[boff]);
        cpasync16(sb + 3 * SBUF + soff, &Xlo[boff]);
    }
    asm volatile("cp.async.commit_group;" ::: "memory");
}

__global__ void __launch_bounds__(256, 1)
gemm_mma_kernel(const bf16* __restrict__ Whi, const bf16* __restrict__ Wlo,
                const bf16* __restrict__ Xhi, const bf16* __restrict__ Xlo,
                int strideIn, int Kpad, int CO, int chanOff, int doRelu,
                bf16* __restrict__ Yhi, bf16* __restrict__ Ylo, int strideOut,
                float* __restrict__ Yfinal) {
    extern __shared__ char smem[];
    uint32_t sb = smem_to_u32(smem);

    int tid = threadIdx.x;
    int wid = tid >> 5;
    int lane = tid & 31;
    int g = lane >> 2;
    int tg = lane & 3;
    int m0 = blockIdx.y * 128;
    int n0 = blockIdx.x * 128;
    int wm = (wid & 1) * 64;
    int wn = (wid >> 1) * 32;

    // ldmatrix lane-address row offsets (within a tile buffer)
    uint32_t aOff[4], bOff[2];
#pragma unroll
    for (int mi = 0; mi < 4; mi++)
        aOff[mi] = (uint32_t)((wm + mi * 16 + (lane & 15)) * PITCH + (lane >> 4) * 16);
#pragma unroll
    for (int np = 0; np < 2; np++)
        bOff[np] = (uint32_t)((wn + np * 16 + (lane & 7) + ((lane >> 4) << 3)) * PITCH
                              + ((lane >> 3) & 1) * 16);

    float d[4][4][4];
#pragma unroll
    for (int mi = 0; mi < 4; mi++)
#pragma unroll
        for (int ni = 0; ni < 4; ni++)
#pragma unroll
            for (int r = 0; r < 4; r++) d[mi][ni][r] = 0.0f;

    int nCh = Kpad >> 6;
    load_stage(sb, 0, 0, m0, n0, Kpad, strideIn, Whi, Wlo, Xhi, Xlo, tid);

    for (int ch = 0; ch < nCh; ch++) {
        if (ch + 1 < nCh) {
            load_stage(sb, (ch + 1) & 1, (ch + 1) << 6, m0, n0, Kpad,
                       strideIn, Whi, Wlo, Xhi, Xlo, tid);
            asm volatile("cp.async.wait_group 1;" ::: "memory");
        } else {
            asm volatile("cp.async.wait_group 0;" ::: "memory");
        }
        __syncthreads();

        uint32_t base = sb + (uint32_t)((ch & 1) * STAGE);
#pragma unroll
        for (int ks = 0; ks < 4; ks++) {
            uint32_t c0 = (uint32_t)(ks * 32);

            uint32_t ah[4][4], al[4][4];
#pragma unroll
            for (int mi = 0; mi < 4; mi++) {
                ldmx4(ah[mi], base + aOff[mi] + c0);
                ldmx4(al[mi], base + SBUF + aOff[mi] + c0);
            }
            uint32_t bh[4][2], bl[4][2];
#pragma unroll
            for (int np = 0; np < 2; np++) {
                ldmx4(&bh[np * 2][0], base + 2 * SBUF + bOff[np] + c0);
                ldmx4(&bl[np * 2][0], base + 3 * SBUF + bOff[np] + c0);
            }
#pragma unroll
            for (int mi = 0; mi < 4; mi++)
#pragma unroll
                for (int ni = 0; ni < 4; ni++) {
                    mma16816(d[mi][ni], ah[mi], bh[ni]);
                    mma16816(d[mi][ni], ah[mi], bl[ni]);
                    mma16816(d[mi][ni], al[mi], bh[ni]);
                }
        }
        __syncthreads();
    }

    // Epilogue
#pragma unroll
    for (int mi = 0; mi < 4; mi++) {
#pragma unroll
        for (int r2 = 0; r2 < 2; r2++) {
            int m = m0 + wm + mi * 16 + g + r2 * 8;
            if (m >= CO) continue;
            float al_ = g_alpha[chanOff + m];
            float bt_ = g_beta[chanOff + m];
#pragma unroll
            for (int ni = 0; ni < 4; ni++) {
#pragma unroll
                for (int c = 0; c < 2; c++) {
                    int n = n0 + wn + ni * 8 + tg * 2 + c;
                    float v = d[mi][ni][r2 * 2 + c] * al_ + bt_;
                    if (doRelu) v = fmaxf(v, 0.0f);
                    if (Yfinal == nullptr) {
                        bf16 h = __float2bfloat16(v);
                        size_t o = (size_t)n * strideOut + m;
                        Yhi[o] = h;
                        Ylo[o] = __float2bfloat16(v - __bfloat162float(h));
                    } else {
                        int b = n / SEGS;
                        int s = n - b * SEGS;
                        Yfinal[((size_t)b * 768 + m) * SEGS + s] = v;
                    }
                }
            }
        }
    }
}

// ---------------------------------------------------------------------------
// sliced (int32) -> float copy into front of output
// ---------------------------------------------------------------------------
__global__ void copy_sliced_kernel(const int* __restrict__ sl,
                                   float* __restrict__ out, int n4) {
    int i = blockIdx.x * blockDim.x + threadIdx.x;
    if (i < n4) {
        int4 v = ((const int4*)sl)[i];
        ((float4*)out)[i] = make_float4((float)v.x, (float)v.y, (float)v.z, (float)v.w);
    }
}

// ---------------------------------------------------------------------------
extern "C" void kernel_launch(void* const* d_in, const int* in_sizes, int n_in,
                              void* d_out, int out_size) {
    const float* x      = (const float*)d_in[0];
    const int*   sliced = (const int*)d_in[1];

    bf16 *bufA_hi, *bufA_lo, *bufB_hi, *bufB_lo, *wHi, *wLo;
    cudaGetSymbolAddress((void**)&bufA_hi, g_bufA_hi);
    cudaGetSymbolAddress((void**)&bufA_lo, g_bufA_lo);
    cudaGetSymbolAddress((void**)&bufB_hi, g_bufB_hi);
    cudaGetSymbolAddress((void**)&bufB_lo, g_bufB_lo);
    cudaGetSymbolAddress((void**)&wHi, g_wHi);
    cudaGetSymbolAddress((void**)&wLo, g_wLo);

    cudaFuncSetAttribute(gemm_mma_kernel,
                         cudaFuncAttributeMaxDynamicSharedMemorySize, GSMEM);

    float* out_f = (float*)d_out;
    size_t front = ((size_t)out_size > H_ELEMS) ? ((size_t)out_size - H_ELEMS) : 0;
    float* h_out = out_f + front;

    // Launch 1: BN fold (all layers)
    BNArgs bn;
    for (int i = 0; i < 5; i++)
        for (int j = 0; j < 5; j++)
            bn.p[i * 5 + j] = (const float*)d_in[2 + 6 * i + 1 + j];
    prep_bn_all_kernel<<<(2208 + 255) / 256, 256>>>(bn);

    // Launch 2: weight prep (all GEMM layers)
    WArgs wa;
    for (int i = 0; i < 4; i++) wa.w[i] = (const float*)d_in[2 + 6 * (i + 1)];
    prep_w_all_kernel<<<(WTOT + 255) / 256, 256>>>(wa);

    // Launches 3-4: segment stats
    zero_stats_kernel<<<(NPOS * 12 / 4 + 255) / 256, 256>>>();
    seg_accum_kernel<<<(BATCH * HW / 4 + 255) / 256, 256>>>(x, sliced);

    // Launch 5: finalize + L0 fused
    const float* w0 = (const float*)d_in[2];
    l0_kernel<<<NPOS, 128>>>(x, w0);

    // Launch 6 (= ncu capture slot): L1 gemm  96(pad128) -> 192
    gemm_mma_kernel<<<dim3(NPOS / 128, 2), 256, GSMEM>>>(
        wHi + WOFF1, wLo + WOFF1, bufA_hi, bufA_lo, 128, 128, 192, 96, 1,
        bufB_hi, bufB_lo, 192, nullptr);

    // L2: 192 -> 384
    gemm_mma_kernel<<<dim3(NPOS / 128, 3), 256, GSMEM>>>(
        wHi + WOFF2, wLo + WOFF2, bufB_hi, bufB_lo, 192, 192, 384, 288, 1,
        bufA_hi, bufA_lo, 384, nullptr);

    // L3: 384 -> 768
    gemm_mma_kernel<<<dim3(NPOS / 128, 6), 256, GSMEM>>>(
        wHi + WOFF3, wLo + WOFF3, bufA_hi, bufA_lo, 384, 384, 768, 672, 1,
        bufB_hi, bufB_lo, 768, nullptr);

    // L4: 768 -> 768 -> final fp32 output [B][768][196]
    gemm_mma_kernel<<<dim3(NPOS / 128, 6), 256, GSMEM>>>(
        wHi + WOFF4, wLo + WOFF4, bufB_hi, bufB_lo, 768, 768, 768, 1440, 0,
        nullptr, nullptr, 0, h_out);

    // sliced copy (independent; placed last to keep gemm L1 at capture slot)
    if (front > 0) {
        int n4 = (int)(front / 4);
        copy_sliced_kernel<<<(n4 + 255) / 256, 256>>>(sliced, out_f, n4);
    }
}

// round 14
// speedup vs baseline: 2.3116x; 1.0161x over previous
#include <cuda_runtime.h>
#include <cuda_bf16.h>
#include <cstdint>
#include <cstddef>

// ---------------------------------------------------------------------------
// Problem constants
// ---------------------------------------------------------------------------
#define BATCH   128
#define HW      50176          // 224*224
#define WIDTH   224
#define SEGS    196            // 14*14
#define NPOS    25088          // BATCH * SEGS
#define H_ELEMS 19267584ull    // 128*768*196

typedef __nv_bfloat16 bf16;

// Weight arena: padded per-layer regions (rows padded to M-tile, K padded to 64)
// L1: 256x128 @0, L2: 384x192 @32768, L3: 768x384 @106496, L4: 768x768 @401408
#define WOFF1 0
#define WOFF2 32768
#define WOFF3 106496
#define WOFF4 401408
#define WTOT  991232

// prep_all work partition
#define PREP_W_ITEMS   WTOT                  // weight split items
#define PREP_BN_ITEMS  2208                  // bn channels
#define PREP_Z_ITEMS   (NPOS * 12 / 4)       // stats zero (float4)
#define PREP_TOTAL     (PREP_W_ITEMS + PREP_BN_ITEMS + PREP_Z_ITEMS)

// ---------------------------------------------------------------------------
// Device-global scratch (allocation forbidden)
// ---------------------------------------------------------------------------
__device__ bf16 g_bufA_hi[(size_t)NPOS * 768];
__device__ bf16 g_bufA_lo[(size_t)NPOS * 768];
__device__ bf16 g_bufB_hi[(size_t)NPOS * 768];
__device__ bf16 g_bufB_lo[(size_t)NPOS * 768];
__device__ bf16 g_wHi[WTOT];
__device__ bf16 g_wLo[WTOT];
__device__ float g_stats2[(size_t)NPOS * 12];
__device__ float g_alpha[2208];
__device__ float g_beta[2208];

// ---------------------------------------------------------------------------
// Helpers (baseline PTX only -- NO tcgen05/TMEM; toolchain targets sm_103 plain)
// ---------------------------------------------------------------------------
__device__ __forceinline__ uint32_t smem_to_u32(const void* smem_ptr) {
    uint32_t addr;
    asm("{ .reg .u64 tmp; cvta.to.shared.u64 tmp, %1; cvt.u32.u64 %0, tmp; }"
        : "=r"(addr) : "l"(smem_ptr));
    return addr;
}

__device__ __forceinline__ void cpasync16(uint32_t saddr, const void* gaddr) {
    asm volatile("cp.async.ca.shared.global [%0], [%1], 16;"
                 :: "r"(saddr), "l"(gaddr) : "memory");
}

__device__ __forceinline__ void mma16816(float* d, const uint32_t* a,
                                         const uint32_t* b) {
    asm volatile(
        "mma.sync.aligned.m16n8k16.row.col.f32.bf16.bf16.f32 "
        "{%0,%1,%2,%3}, {%4,%5,%6,%7}, {%8,%9}, {%0,%1,%2,%3};"
        : "+f"(d[0]), "+f"(d[1]), "+f"(d[2]), "+f"(d[3])
        : "r"(a[0]), "r"(a[1]), "r"(a[2]), "r"(a[3]), "r"(b[0]), "r"(b[1]));
}

__device__ __forceinline__ void ldmx4(uint32_t* r, uint32_t addr) {
    asm volatile(
        "ldmatrix.sync.aligned.m8n8.x4.shared.b16 {%0,%1,%2,%3}, [%4];"
        : "=r"(r[0]), "=r"(r[1]), "=r"(r[2]), "=r"(r[3]) : "r"(addr));
}

// ---------------------------------------------------------------------------
// Fused prep: weight split + BN fold + stats zero, single launch
// ---------------------------------------------------------------------------
struct PrepArgs {
    const float* w[4];     // w1..w4
    const float* p[25];    // per layer: b, g, be, rm, rv
};

__global__ void prep_all_kernel(PrepArgs a) {
    int i = blockIdx.x * blockDim.x + threadIdx.x;
    if (i < PREP_W_ITEMS) {
        // --- weight split ---
        const int segB[5] = {0, WOFF2, WOFF3, WOFF4, WTOT};
        const int CO[4]   = {192, 384, 768, 768};
        const int K[4]    = {96, 192, 384, 768};
        const int KP[4]   = {128, 192, 384, 768};
        int l = 0;
        while (l < 3 && i >= segB[l + 1]) l++;
        int loc = i - segB[l];
        int co = loc / KP[l];
        int k  = loc - co * KP[l];
        float v = (co < CO[l] && k < K[l]) ? a.w[l][co * K[l] + k] : 0.0f;
        bf16 h = __float2bfloat16(v);
        g_wHi[i] = h;
        g_wLo[i] = __float2bfloat16(v - __bfloat162float(h));
    } else if (i < PREP_W_ITEMS + PREP_BN_ITEMS) {
        // --- BN fold ---
        int j = i - PREP_W_ITEMS;
        const int cos[5]  = {96, 192, 384, 768, 768};
        const int offs[5] = {0, 96, 288, 672, 1440};
        int l = 0;
        while (l < 4 && j >= offs[l + 1]) l++;
        int c = j - offs[l];
        if (c < cos[l]) {
            const float* bb = a.p[l * 5 + 0];
            const float* gg = a.p[l * 5 + 1];
            const float* be = a.p[l * 5 + 2];
            const float* rm = a.p[l * 5 + 3];
            const float* rv = a.p[l * 5 + 4];
            float al = gg[c] / sqrtf(rv[c] + 1e-5f);
            g_alpha[j] = al;
            g_beta[j]  = (bb[c] - rm[c]) * al + be[c];
        }
    } else if (i < PREP_TOTAL) {
        // --- zero stats ---
        int j = i - PREP_W_ITEMS - PREP_BN_ITEMS;
        ((float4*)g_stats2)[j] = make_float4(0.f, 0.f, 0.f, 0.f);
    }
}

// ---------------------------------------------------------------------------
// Segment accumulation via global vector reductions
// ---------------------------------------------------------------------------
__device__ __forceinline__ void red4(float* p, float a, float b, float c, float d) {
    asm volatile("red.global.add.v4.f32 [%0], {%1, %2, %3, %4};"
                 :: "l"(__cvta_generic_to_global(p)),
                    "f"(a), "f"(b), "f"(c), "f"(d) : "memory");
}

__global__ void seg_accum_kernel(const float* __restrict__ x,
                                 const int* __restrict__ sliced) {
    int t = blockIdx.x * blockDim.x + threadIdx.x;
    if (t >= BATCH * HW / 4) return;
    int g = t * 4;
    int b = g / HW;
    int p = g - b * HW;

    int4 id4 = *(const int4*)&sliced[g];
    const float* xr = x + (size_t)b * 3 * HW;
    float4 c0 = *(const float4*)&xr[p];
    float4 c1 = *(const float4*)&xr[HW + p];
    float4 c2 = *(const float4*)&xr[2 * HW + p];

    float r = (float)(p / WIDTH);
    float cb = (float)(p % WIDTH);

    int   ids[4] = {id4.x, id4.y, id4.z, id4.w};
    float a0[4] = {c0.x, c0.y, c0.z, c0.w};
    float a1[4] = {c1.x, c1.y, c1.z, c1.w};
    float a2[4] = {c2.x, c2.y, c2.z, c2.w};

#pragma unroll
    for (int u = 0; u < 4; u++) {
        float* base = &g_stats2[((size_t)b * SEGS + ids[u]) * 12];
        red4(base,     1.0f, r, cb + (float)u, a0[u]);
        red4(base + 4, a1[u], a2[u], a0[u] * a0[u], a1[u] * a1[u]);
        atomicAdd(base + 8, a2[u] * a2[u]);
    }
}

// ---------------------------------------------------------------------------
// Layer 0 fused with finalize: per pos, compute features from stats, then
// 11 -> 96 dot products + BN + ReLU -> bufA split bf16 (stride 128, zero pad)
// ---------------------------------------------------------------------------
__global__ void l0_kernel(const float* __restrict__ x,
                          const float* __restrict__ w0) {
    __shared__ float f[11];
    int pos = blockIdx.x;
    int co = threadIdx.x;   // 0..127

    if (co == 0) {
        int b = pos / SEGS;
        const float* st = &g_stats2[(size_t)pos * 12];
        float cnt  = st[0];
        float inv  = 1.0f / fmaxf(cnt, 1.0f);
        float mrow = st[1] * inv;
        float mcol = st[2] * inv;
        float m0 = st[3] * inv, m1 = st[4] * inv, m2 = st[5] * inv;
        float dnm = 1.0f / fmaxf(cnt - 1.0f, 1.0f);
        float v0 = (st[6] - cnt * m0 * m0) * dnm;
        float v1 = (st[7] - cnt * m1 * m1) * dnm;
        float v2 = (st[8] - cnt * m2 * m2) * dnm;
        float s0 = (cnt > 1.0f) ? sqrtf(fmaxf(v0, 0.0f)) : 0.0f;
        float s1 = (cnt > 1.0f) ? sqrtf(fmaxf(v1, 0.0f)) : 0.0f;
        float s2 = (cnt > 1.0f) ? sqrtf(fmaxf(v2, 0.0f)) : 0.0f;
        int ri = min(max((int)mrow, 0), WIDTH - 1);
        int ci = min(max((int)mcol, 0), WIDTH - 1);
        const float* xr = x + (size_t)b * 3 * HW;
        int po = ri * WIDTH + ci;
        float mask = (cnt > 0.0f) ? 1.0f : 0.0f;
        f[0] = mrow * mask;  f[1] = mcol * mask;
        f[2] = m0 * mask;    f[3] = m1 * mask;    f[4] = m2 * mask;
        f[5] = s0 * mask;    f[6] = s1 * mask;    f[7] = s2 * mask;
        f[8] = xr[po] * mask; f[9] = xr[HW + po] * mask; f[10] = xr[2 * HW + po] * mask;
    }
    __syncthreads();

    bf16 h = __float2bfloat16(0.0f);
    bf16 l = h;
    if (co < 96) {
        float v = 0.0f;
#pragma unroll
        for (int k = 0; k < 11; k++) v += __ldg(&w0[co * 11 + k]) * f[k];
        v = fmaxf(v * g_alpha[co] + g_beta[co], 0.0f);
        h = __float2bfloat16(v);
        l = __float2bfloat16(v - __bfloat162float(h));
    }
    g_bufA_hi[(size_t)pos * 128 + co] = h;
    g_bufA_lo[(size_t)pos * 128 + co] = l;
}

// ---------------------------------------------------------------------------
// Split-bf16 HMMA GEMM + BN(+ReLU), ldmatrix fragments, BK=64, double buffer
//   D[m,n] = sum_k W[m,k]*X[n,k]; 3 mma per frag pair (hh + hl + lh)
//   CTA 128x128, 256 threads = 8 warps (2 M x 4 N), warp tile 64x32
// ---------------------------------------------------------------------------
#define PITCH 144                      // bytes/row: 64 bf16 = 128 B + 16 pad
#define SBUF  (128 * PITCH)            // 18432 B per tile
#define STAGE (4 * SBUF)               // AH, AL, BH, BL = 73728 B
#define GSMEM (2 * STAGE)              // 147456 B

__device__ __forceinline__ void load_stage(
    uint32_t sb, int st, int k0, int m0, int n0, int Kpad, int strideIn,
    const bf16* __restrict__ Whi, const bf16* __restrict__ Wlo,
    const bf16* __restrict__ Xhi, const bf16* __restrict__ Xlo, int tid) {
#pragma unroll
    for (int i = 0; i < 4; i++) {
        int lin = i * 256 + tid;       // 0..1023
        int row = lin >> 3;
        int kc  = lin & 7;
        uint32_t soff = (uint32_t)(st * STAGE + row * PITCH + kc * 16);
        size_t aoff = (size_t)(m0 + row) * Kpad + k0 + kc * 8;
        size_t boff = (size_t)(n0 + row) * strideIn + k0 + kc * 8;
        cpasync16(sb + soff,            &Whi[aoff]);
        cpasync16(sb + SBUF + soff,     &Wlo[aoff]);
        cpasync16(sb + 2 * SBUF + soff, &Xhi[boff]);
        cpasync16(sb + 3 * SBUF + soff, &Xlo[boff]);
    }
    asm volatile("cp.async.commit_group;" ::: "memory");
}

__global__ void __launch_bounds__(256, 1)
gemm_mma_kernel(const bf16* __restrict__ Whi, const bf16* __restrict__ Wlo,
                const bf16* __restrict__ Xhi, const bf16* __restrict__ Xlo,
                int strideIn, int Kpad, int CO, int chanOff, int doRelu,
                bf16* __restrict__ Yhi, bf16* __restrict__ Ylo, int strideOut,
                float* __restrict__ Yfinal) {
    extern __shared__ char smem[];
    uint32_t sb = smem_to_u32(smem);

    int tid = threadIdx.x;
    int wid = tid >> 5;
    int lane = tid & 31;
    int g = lane >> 2;
    int tg = lane & 3;
    int m0 = blockIdx.y * 128;
    int n0 = blockIdx.x * 128;
    int wm = (wid & 1) * 64;
    int wn = (wid >> 1) * 32;

    // ldmatrix lane-address row offsets (within a tile buffer)
    uint32_t aOff[4], bOff[2];
#pragma unroll
    for (int mi = 0; mi < 4; mi++)
        aOff[mi] = (uint32_t)((wm + mi * 16 + (lane & 15)) * PITCH + (lane >> 4) * 16);
#pragma unroll
    for (int np = 0; np < 2; np++)
        bOff[np] = (uint32_t)((wn + np * 16 + (lane & 7) + ((lane >> 4) << 3)) * PITCH
                              + ((lane >> 3) & 1) * 16);

    float d[4][4][4];
#pragma unroll
    for (int mi = 0; mi < 4; mi++)
#pragma unroll
        for (int ni = 0; ni < 4; ni++)
#pragma unroll
            for (int r = 0; r < 4; r++) d[mi][ni][r] = 0.0f;

    int nCh = Kpad >> 6;
    load_stage(sb, 0, 0, m0, n0, Kpad, strideIn, Whi, Wlo, Xhi, Xlo, tid);

    for (int ch = 0; ch < nCh; ch++) {
        if (ch + 1 < nCh) {
            load_stage(sb, (ch + 1) & 1, (ch + 1) << 6, m0, n0, Kpad,
                       strideIn, Whi, Wlo, Xhi, Xlo, tid);
            asm volatile("cp.async.wait_group 1;" ::: "memory");
        } else {
            asm volatile("cp.async.wait_group 0;" ::: "memory");
        }
        __syncthreads();

        uint32_t base = sb + (uint32_t)((ch & 1) * STAGE);
#pragma unroll
        for (int ks = 0; ks < 4; ks++) {
            uint32_t c0 = (uint32_t)(ks * 32);

            uint32_t ah[4][4], al[4][4];
#pragma unroll
            for (int mi = 0; mi < 4; mi++) {
                ldmx4(ah[mi], base + aOff[mi] + c0);
                ldmx4(al[mi], base + SBUF + aOff[mi] + c0);
            }
            uint32_t bh[4][2], bl[4][2];
#pragma unroll
            for (int np = 0; np < 2; np++) {
                ldmx4(&bh[np * 2][0], base + 2 * SBUF + bOff[np] + c0);
                ldmx4(&bl[np * 2][0], base + 3 * SBUF + bOff[np] + c0);
            }
#pragma unroll
            for (int mi = 0; mi < 4; mi++)
#pragma unroll
                for (int ni = 0; ni < 4; ni++) {
                    mma16816(d[mi][ni], ah[mi], bh[ni]);
                    mma16816(d[mi][ni], ah[mi], bl[ni]);
                    mma16816(d[mi][ni], al[mi], bh[ni]);
                }
        }
        __syncthreads();
    }

    // Epilogue
#pragma unroll
    for (int mi = 0; mi < 4; mi++) {
#pragma unroll
        for (int r2 = 0; r2 < 2; r2++) {
            int m = m0 + wm + mi * 16 + g + r2 * 8;
            if (m >= CO) continue;
            float al_ = g_alpha[chanOff + m];
            float bt_ = g_beta[chanOff + m];
#pragma unroll
            for (int ni = 0; ni < 4; ni++) {
#pragma unroll
                for (int c = 0; c < 2; c++) {
                    int n = n0 + wn + ni * 8 + tg * 2 + c;
                    float v = d[mi][ni][r2 * 2 + c] * al_ + bt_;
                    if (doRelu) v = fmaxf(v, 0.0f);
                    if (Yfinal == nullptr) {
                        bf16 h = __float2bfloat16(v);
                        size_t o = (size_t)n * strideOut + m;
                        Yhi[o] = h;
                        Ylo[o] = __float2bfloat16(v - __bfloat162float(h));
                    } else {
                        int b = n / SEGS;
                        int s = n - b * SEGS;
                        Yfinal[((size_t)b * 768 + m) * SEGS + s] = v;
                    }
                }
            }
        }
    }
}

// ---------------------------------------------------------------------------
// sliced (int32) -> float copy into front of output
// ---------------------------------------------------------------------------
__global__ void copy_sliced_kernel(const int* __restrict__ sl,
                                   float* __restrict__ out, int n4) {
    int i = blockIdx.x * blockDim.x + threadIdx.x;
    if (i < n4) {
        int4 v = ((const int4*)sl)[i];
        ((float4*)out)[i] = make_float4((float)v.x, (float)v.y, (float)v.z, (float)v.w);
    }
}

// ---------------------------------------------------------------------------
extern "C" void kernel_launch(void* const* d_in, const int* in_sizes, int n_in,
                              void* d_out, int out_size) {
    const float* x      = (const float*)d_in[0];
    const int*   sliced = (const int*)d_in[1];

    bf16 *bufA_hi, *bufA_lo, *bufB_hi, *bufB_lo, *wHi, *wLo;
    cudaGetSymbolAddress((void**)&bufA_hi, g_bufA_hi);
    cudaGetSymbolAddress((void**)&bufA_lo, g_bufA_lo);
    cudaGetSymbolAddress((void**)&bufB_hi, g_bufB_hi);
    cudaGetSymbolAddress((void**)&bufB_lo, g_bufB_lo);
    cudaGetSymbolAddress((void**)&wHi, g_wHi);
    cudaGetSymbolAddress((void**)&wLo, g_wLo);

    cudaFuncSetAttribute(gemm_mma_kernel,
                         cudaFuncAttributeMaxDynamicSharedMemorySize, GSMEM);

    float* out_f = (float*)d_out;
    size_t front = ((size_t)out_size > H_ELEMS) ? ((size_t)out_size - H_ELEMS) : 0;
    float* h_out = out_f + front;

    // Launch 1: fused prep (weight split + BN fold + stats zero)
    PrepArgs pa;
    for (int i = 0; i < 4; i++) pa.w[i] = (const float*)d_in[2 + 6 * (i + 1)];
    for (int i = 0; i < 5; i++)
        for (int j = 0; j < 5; j++)
            pa.p[i * 5 + j] = (const float*)d_in[2 + 6 * i + 1 + j];
    prep_all_kernel<<<(PREP_TOTAL + 255) / 256, 256>>>(pa);

    // Launch 2: segment stats accumulation
    seg_accum_kernel<<<(BATCH * HW / 4 + 255) / 256, 256>>>(x, sliced);

    // Launch 3: finalize + L0 fused
    const float* w0 = (const float*)d_in[2];
    l0_kernel<<<NPOS, 128>>>(x, w0);

    // Launch 4 (= observed ncu capture slot): L1 gemm  96(pad128) -> 192
    gemm_mma_kernel<<<dim3(NPOS / 128, 2), 256, GSMEM>>>(
        wHi + WOFF1, wLo + WOFF1, bufA_hi, bufA_lo, 128, 128, 192, 96, 1,
        bufB_hi, bufB_lo, 192, nullptr);

    // L2: 192 -> 384
    gemm_mma_kernel<<<dim3(NPOS / 128, 3), 256, GSMEM>>>(
        wHi + WOFF2, wLo + WOFF2, bufB_hi, bufB_lo, 192, 192, 384, 288, 1,
        bufA_hi, bufA_lo, 384, nullptr);

    // L3: 384 -> 768
    gemm_mma_kernel<<<dim3(NPOS / 128, 6), 256, GSMEM>>>(
        wHi + WOFF3, wLo + WOFF3, bufA_hi, bufA_lo, 384, 384, 768, 672, 1,
        bufB_hi, bufB_lo, 768, nullptr);

    // L4: 768 -> 768 -> final fp32 output [B][768][196]
    gemm_mma_kernel<<<dim3(NPOS / 128, 6), 256, GSMEM>>>(
        wHi + WOFF4, wLo + WOFF4, bufB_hi, bufB_lo, 768, 768, 768, 1440, 0,
        nullptr, nullptr, 0, h_out);

    // sliced copy (independent; last)
    if (front > 0) {
        int n4 = (int)(front / 4);
        copy_sliced_kernel<<<(n4 + 255) / 256, 256>>>(sliced, out_f, n4);
    }
}

// round 15
// speedup vs baseline: 2.4096x; 1.0424x over previous
#include <cuda_runtime.h>
#include <cuda_bf16.h>
#include <cstdint>
#include <cstddef>

// ---------------------------------------------------------------------------
// Problem constants
// ---------------------------------------------------------------------------
#define BATCH   128
#define HW      50176          // 224*224
#define WIDTH   224
#define SEGS    196            // 14*14
#define NPOS    25088          // BATCH * SEGS
#define H_ELEMS 19267584ull    // 128*768*196

typedef __nv_bfloat16 bf16;

// Weight arena: padded per-layer regions
// L1: 256x96 @0, L2: 384x192 @24576, L3: 768x384 @98304, L4: 768x768 @393216
#define WOFF1 0
#define WOFF2 24576
#define WOFF3 98304
#define WOFF4 393216
#define WTOT  983040

// prep_all work partition
#define PREP_W_ITEMS   WTOT
#define PREP_BN_ITEMS  2208
#define PREP_Z_ITEMS   (NPOS * 12 / 4)
#define PREP_TOTAL     (PREP_W_ITEMS + PREP_BN_ITEMS + PREP_Z_ITEMS)

// ---------------------------------------------------------------------------
// Device-global scratch (allocation forbidden)
// ---------------------------------------------------------------------------
__device__ bf16 g_bufA_hi[(size_t)NPOS * 768];
__device__ bf16 g_bufA_lo[(size_t)NPOS * 768];
__device__ bf16 g_bufB_hi[(size_t)NPOS * 768];
__device__ bf16 g_bufB_lo[(size_t)NPOS * 768];
__device__ bf16 g_wHi[WTOT];
__device__ bf16 g_wLo[WTOT];
__device__ float g_stats2[(size_t)NPOS * 12];
__device__ float g_alpha[2208];
__device__ float g_beta[2208];

// ---------------------------------------------------------------------------
// Helpers (baseline PTX only -- NO tcgen05/TMEM; toolchain targets sm_103 plain)
// ---------------------------------------------------------------------------
__device__ __forceinline__ uint32_t smem_to_u32(const void* smem_ptr) {
    uint32_t addr;
    asm("{ .reg .u64 tmp; cvta.to.shared.u64 tmp, %1; cvt.u32.u64 %0, tmp; }"
        : "=r"(addr) : "l"(smem_ptr));
    return addr;
}

__device__ __forceinline__ void cpasync16(uint32_t saddr, const void* gaddr) {
    asm volatile("cp.async.ca.shared.global [%0], [%1], 16;"
                 :: "r"(saddr), "l"(gaddr) : "memory");
}

__device__ __forceinline__ void mma16816(float* d, const uint32_t* a,
                                         const uint32_t* b) {
    asm volatile(
        "mma.sync.aligned.m16n8k16.row.col.f32.bf16.bf16.f32 "
        "{%0,%1,%2,%3}, {%4,%5,%6,%7}, {%8,%9}, {%0,%1,%2,%3};"
        : "+f"(d[0]), "+f"(d[1]), "+f"(d[2]), "+f"(d[3])
        : "r"(a[0]), "r"(a[1]), "r"(a[2]), "r"(a[3]), "r"(b[0]), "r"(b[1]));
}

__device__ __forceinline__ void ldmx4(uint32_t* r, uint32_t addr) {
    asm volatile(
        "ldmatrix.sync.aligned.m8n8.x4.shared.b16 {%0,%1,%2,%3}, [%4];"
        : "=r"(r[0]), "=r"(r[1]), "=r"(r[2]), "=r"(r[3]) : "r"(addr));
}

// ---------------------------------------------------------------------------
// Fused prep: weight split + BN fold + stats zero, single launch
// ---------------------------------------------------------------------------
struct PrepArgs {
    const float* w[4];     // w1..w4
    const float* p[25];    // per layer: b, g, be, rm, rv
};

__global__ void prep_all_kernel(PrepArgs a) {
    int i = blockIdx.x * blockDim.x + threadIdx.x;
    if (i < PREP_W_ITEMS) {
        const int segB[5] = {0, WOFF2, WOFF3, WOFF4, WTOT};
        const int CO[4]   = {192, 384, 768, 768};
        const int K[4]    = {96, 192, 384, 768};
        const int KP[4]   = {96, 192, 384, 768};
        int l = 0;
        while (l < 3 && i >= segB[l + 1]) l++;
        int loc = i - segB[l];
        int co = loc / KP[l];
        int k  = loc - co * KP[l];
        float v = (co < CO[l] && k < K[l]) ? a.w[l][co * K[l] + k] : 0.0f;
        bf16 h = __float2bfloat16(v);
        g_wHi[i] = h;
        g_wLo[i] = __float2bfloat16(v - __bfloat162float(h));
    } else if (i < PREP_W_ITEMS + PREP_BN_ITEMS) {
        int j = i - PREP_W_ITEMS;
        const int cos[5]  = {96, 192, 384, 768, 768};
        const int offs[5] = {0, 96, 288, 672, 1440};
        int l = 0;
        while (l < 4 && j >= offs[l + 1]) l++;
        int c = j - offs[l];
        if (c < cos[l]) {
            const float* bb = a.p[l * 5 + 0];
            const float* gg = a.p[l * 5 + 1];
            const float* be = a.p[l * 5 + 2];
            const float* rm = a.p[l * 5 + 3];
            const float* rv = a.p[l * 5 + 4];
            float al = gg[c] / sqrtf(rv[c] + 1e-5f);
            g_alpha[j] = al;
            g_beta[j]  = (bb[c] - rm[c]) * al + be[c];
        }
    } else if (i < PREP_TOTAL) {
        int j = i - PREP_W_ITEMS - PREP_BN_ITEMS;
        ((float4*)g_stats2)[j] = make_float4(0.f, 0.f, 0.f, 0.f);
    }
}

// ---------------------------------------------------------------------------
// Segment accumulation via global vector reductions
// ---------------------------------------------------------------------------
__device__ __forceinline__ void red4(float* p, float a, float b, float c, float d) {
    asm volatile("red.global.add.v4.f32 [%0], {%1, %2, %3, %4};"
                 :: "l"(__cvta_generic_to_global(p)),
                    "f"(a), "f"(b), "f"(c), "f"(d) : "memory");
}

__global__ void seg_accum_kernel(const float* __restrict__ x,
                                 const int* __restrict__ sliced) {
    int t = blockIdx.x * blockDim.x + threadIdx.x;
    if (t >= BATCH * HW / 4) return;
    int g = t * 4;
    int b = g / HW;
    int p = g - b * HW;

    int4 id4 = *(const int4*)&sliced[g];
    const float* xr = x + (size_t)b * 3 * HW;
    float4 c0 = *(const float4*)&xr[p];
    float4 c1 = *(const float4*)&xr[HW + p];
    float4 c2 = *(const float4*)&xr[2 * HW + p];

    float r = (float)(p / WIDTH);
    float cb = (float)(p % WIDTH);

    int   ids[4] = {id4.x, id4.y, id4.z, id4.w};
    float a0[4] = {c0.x, c0.y, c0.z, c0.w};
    float a1[4] = {c1.x, c1.y, c1.z, c1.w};
    float a2[4] = {c2.x, c2.y, c2.z, c2.w};

#pragma unroll
    for (int u = 0; u < 4; u++) {
        float* base = &g_stats2[((size_t)b * SEGS + ids[u]) * 12];
        red4(base,     1.0f, r, cb + (float)u, a0[u]);
        red4(base + 4, a1[u], a2[u], a0[u] * a0[u], a1[u] * a1[u]);
        atomicAdd(base + 8, a2[u] * a2[u]);
    }
}

// ---------------------------------------------------------------------------
// Layer 0 fused with finalize
// ---------------------------------------------------------------------------
__global__ void l0_kernel(const float* __restrict__ x,
                          const float* __restrict__ w0) {
    __shared__ float f[11];
    int pos = blockIdx.x;
    int co = threadIdx.x;   // 0..127

    if (co == 0) {
        int b = pos / SEGS;
        const float* st = &g_stats2[(size_t)pos * 12];
        float cnt  = st[0];
        float inv  = 1.0f / fmaxf(cnt, 1.0f);
        float mrow = st[1] * inv;
        float mcol = st[2] * inv;
        float m0 = st[3] * inv, m1 = st[4] * inv, m2 = st[5] * inv;
        float dnm = 1.0f / fmaxf(cnt - 1.0f, 1.0f);
        float v0 = (st[6] - cnt * m0 * m0) * dnm;
        float v1 = (st[7] - cnt * m1 * m1) * dnm;
        float v2 = (st[8] - cnt * m2 * m2) * dnm;
        float s0 = (cnt > 1.0f) ? sqrtf(fmaxf(v0, 0.0f)) : 0.0f;
        float s1 = (cnt > 1.0f) ? sqrtf(fmaxf(v1, 0.0f)) : 0.0f;
        float s2 = (cnt > 1.0f) ? sqrtf(fmaxf(v2, 0.0f)) : 0.0f;
        int ri = min(max((int)mrow, 0), WIDTH - 1);
        int ci = min(max((int)mcol, 0), WIDTH - 1);
        const float* xr = x + (size_t)b * 3 * HW;
        int po = ri * WIDTH + ci;
        float mask = (cnt > 0.0f) ? 1.0f : 0.0f;
        f[0] = mrow * mask;  f[1] = mcol * mask;
        f[2] = m0 * mask;    f[3] = m1 * mask;    f[4] = m2 * mask;
        f[5] = s0 * mask;    f[6] = s1 * mask;    f[7] = s2 * mask;
        f[8] = xr[po] * mask; f[9] = xr[HW + po] * mask; f[10] = xr[2 * HW + po] * mask;
    }
    __syncthreads();

    bf16 h = __float2bfloat16(0.0f);
    bf16 l = h;
    if (co < 96) {
        float v = 0.0f;
#pragma unroll
        for (int k = 0; k < 11; k++) v += __ldg(&w0[co * 11 + k]) * f[k];
        v = fmaxf(v * g_alpha[co] + g_beta[co], 0.0f);
        h = __float2bfloat16(v);
        l = __float2bfloat16(v - __bfloat162float(h));
    }
    g_bufA_hi[(size_t)pos * 128 + co] = h;
    g_bufA_lo[(size_t)pos * 128 + co] = l;
}

// ---------------------------------------------------------------------------
// Split-bf16 HMMA GEMM + BN(+ReLU), ldmatrix fragments, BK=32, double buffer,
// 2 CTAs/SM (smem 80KB/CTA, regs capped via __launch_bounds__(256, 2)).
//   Phased inner loop (hh -> lh -> hl) keeps only 2 operand sets live.
// ---------------------------------------------------------------------------
#define PITCH 80                       // bytes/row: 32 bf16 = 64 B + 16 pad
#define SBUF  (128 * PITCH)            // 10240 B per tile
#define STAGE (4 * SBUF)               // AH, AL, BH, BL = 40960 B
#define GSMEM (2 * STAGE)              // 81920 B

__device__ __forceinline__ void load_stage(
    uint32_t sb, int st, int k0, int m0, int n0, int Kpad, int strideIn,
    const bf16* __restrict__ Whi, const bf16* __restrict__ Wlo,
    const bf16* __restrict__ Xhi, const bf16* __restrict__ Xlo, int tid) {
#pragma unroll
    for (int i = 0; i < 2; i++) {
        int lin = i * 256 + tid;       // 0..511
        int row = lin >> 2;
        int kc  = lin & 3;
        uint32_t soff = (uint32_t)(st * STAGE + row * PITCH + kc * 16);
        size_t aoff = (size_t)(m0 + row) * Kpad + k0 + kc * 8;
        size_t boff = (size_t)(n0 + row) * strideIn + k0 + kc * 8;
        cpasync16(sb + soff,            &Whi[aoff]);
        cpasync16(sb + SBUF + soff,     &Wlo[aoff]);
        cpasync16(sb + 2 * SBUF + soff, &Xhi[boff]);
        cpasync16(sb + 3 * SBUF + soff, &Xlo[boff]);
    }
    asm volatile("cp.async.commit_group;" ::: "memory");
}

__global__ void __launch_bounds__(256, 2)
gemm_mma_kernel(const bf16* __restrict__ Whi, const bf16* __restrict__ Wlo,
                const bf16* __restrict__ Xhi, const bf16* __restrict__ Xlo,
                int strideIn, int Kpad, int CO, int chanOff, int doRelu,
                bf16* __restrict__ Yhi, bf16* __restrict__ Ylo, int strideOut,
                float* __restrict__ Yfinal) {
    extern __shared__ char smem[];
    uint32_t sb = smem_to_u32(smem);

    int tid = threadIdx.x;
    int wid = tid >> 5;
    int lane = tid & 31;
    int g = lane >> 2;
    int tg = lane & 3;
    int m0 = blockIdx.y * 128;
    int n0 = blockIdx.x * 128;
    int wm = (wid & 1) * 64;
    int wn = (wid >> 1) * 32;

    // ldmatrix lane-address offsets (within a tile buffer)
    uint32_t aOff[4], bOff[2];
#pragma unroll
    for (int mi = 0; mi < 4; mi++)
        aOff[mi] = (uint32_t)((wm + mi * 16 + (lane & 15)) * PITCH + (lane >> 4) * 16);
#pragma unroll
    for (int np = 0; np < 2; np++)
        bOff[np] = (uint32_t)((wn + np * 16 + (lane & 7) + ((lane >> 4) << 3)) * PITCH
                              + ((lane >> 3) & 1) * 16);

    float d[4][4][4];
#pragma unroll
    for (int mi = 0; mi < 4; mi++)
#pragma unroll
        for (int ni = 0; ni < 4; ni++)
#pragma unroll
            for (int r = 0; r < 4; r++) d[mi][ni][r] = 0.0f;

    int nCh = Kpad >> 5;
    load_stage(sb, 0, 0, m0, n0, Kpad, strideIn, Whi, Wlo, Xhi, Xlo, tid);

    for (int ch = 0; ch < nCh; ch++) {
        if (ch + 1 < nCh) {
            load_stage(sb, (ch + 1) & 1, (ch + 1) << 5, m0, n0, Kpad,
                       strideIn, Whi, Wlo, Xhi, Xlo, tid);
            asm volatile("cp.async.wait_group 1;" ::: "memory");
        } else {
            asm volatile("cp.async.wait_group 0;" ::: "memory");
        }
        __syncthreads();

        uint32_t base = sb + (uint32_t)((ch & 1) * STAGE);
#pragma unroll
        for (int ks = 0; ks < 2; ks++) {
            uint32_t c0 = (uint32_t)(ks * 32);

            // Phase 1: hh (ah, bh live)
            uint32_t ah[4][4];
            uint32_t bb[4][2];
#pragma unroll
            for (int mi = 0; mi < 4; mi++) ldmx4(ah[mi], base + aOff[mi] + c0);
#pragma unroll
            for (int np = 0; np < 2; np++)
                ldmx4(&bb[np * 2][0], base + 2 * SBUF + bOff[np] + c0);
#pragma unroll
            for (int mi = 0; mi < 4; mi++)
#pragma unroll
                for (int ni = 0; ni < 4; ni++) mma16816(d[mi][ni], ah[mi], bb[ni]);

            // Phase 2: lh (al transient, bh still live)
            {
                uint32_t al[4][4];
#pragma unroll
                for (int mi = 0; mi < 4; mi++)
                    ldmx4(al[mi], base + SBUF + aOff[mi] + c0);
#pragma unroll
                for (int mi = 0; mi < 4; mi++)
#pragma unroll
                    for (int ni = 0; ni < 4; ni++) mma16816(d[mi][ni], al[mi], bb[ni]);
            }

            // Phase 3: hl (bl overwrites bh slot; ah still live)
#pragma unroll
            for (int np = 0; np < 2; np++)
                ldmx4(&bb[np * 2][0], base + 3 * SBUF + bOff[np] + c0);
#pragma unroll
            for (int mi = 0; mi < 4; mi++)
#pragma unroll
                for (int ni = 0; ni < 4; ni++) mma16816(d[mi][ni], ah[mi], bb[ni]);
        }
        __syncthreads();
    }

    // Epilogue
#pragma unroll
    for (int mi = 0; mi < 4; mi++) {
#pragma unroll
        for (int r2 = 0; r2 < 2; r2++) {
            int m = m0 + wm + mi * 16 + g + r2 * 8;
            if (m >= CO) continue;
            float al_ = g_alpha[chanOff + m];
            float bt_ = g_beta[chanOff + m];
#pragma unroll
            for (int ni = 0; ni < 4; ni++) {
#pragma unroll
                for (int c = 0; c < 2; c++) {
                    int n = n0 + wn + ni * 8 + tg * 2 + c;
                    float v = d[mi][ni][r2 * 2 + c] * al_ + bt_;
                    if (doRelu) v = fmaxf(v, 0.0f);
                    if (Yfinal == nullptr) {
                        bf16 h = __float2bfloat16(v);
                        size_t o = (size_t)n * strideOut + m;
                        Yhi[o] = h;
                        Ylo[o] = __float2bfloat16(v - __bfloat162float(h));
                    } else {
                        int b = n / SEGS;
                        int s = n - b * SEGS;
                        Yfinal[((size_t)b * 768 + m) * SEGS + s] = v;
                    }
                }
            }
        }
    }
}

// ---------------------------------------------------------------------------
// sliced (int32) -> float copy into front of output
// ---------------------------------------------------------------------------
__global__ void copy_sliced_kernel(const int* __restrict__ sl,
                                   float* __restrict__ out, int n4) {
    int i = blockIdx.x * blockDim.x + threadIdx.x;
    if (i < n4) {
        int4 v = ((const int4*)sl)[i];
        ((float4*)out)[i] = make_float4((float)v.x, (float)v.y, (float)v.z, (float)v.w);
    }
}

// ---------------------------------------------------------------------------
extern "C" void kernel_launch(void* const* d_in, const int* in_sizes, int n_in,
                              void* d_out, int out_size) {
    const float* x      = (const float*)d_in[0];
    const int*   sliced = (const int*)d_in[1];

    bf16 *bufA_hi, *bufA_lo, *bufB_hi, *bufB_lo, *wHi, *wLo;
    cudaGetSymbolAddress((void**)&bufA_hi, g_bufA_hi);
    cudaGetSymbolAddress((void**)&bufA_lo, g_bufA_lo);
    cudaGetSymbolAddress((void**)&bufB_hi, g_bufB_hi);
    cudaGetSymbolAddress((void**)&bufB_lo, g_bufB_lo);
    cudaGetSymbolAddress((void**)&wHi, g_wHi);
    cudaGetSymbolAddress((void**)&wLo, g_wLo);

    cudaFuncSetAttribute(gemm_mma_kernel,
                         cudaFuncAttributeMaxDynamicSharedMemorySize, GSMEM);

    float* out_f = (float*)d_out;
    size_t front = ((size_t)out_size > H_ELEMS) ? ((size_t)out_size - H_ELEMS) : 0;
    float* h_out = out_f + front;

    // Launch 1: fused prep (weight split + BN fold + stats zero)
    PrepArgs pa;
    for (int i = 0; i < 4; i++) pa.w[i] = (const float*)d_in[2 + 6 * (i + 1)];
    for (int i = 0; i < 5; i++)
        for (int j = 0; j < 5; j++)
            pa.p[i * 5 + j] = (const float*)d_in[2 + 6 * i + 1 + j];
    prep_all_kernel<<<(PREP_TOTAL + 255) / 256, 256>>>(pa);

    // Launch 2: segment stats accumulation
    seg_accum_kernel<<<(BATCH * HW / 4 + 255) / 256, 256>>>(x, sliced);

    // Launch 3: finalize + L0 fused
    const float* w0 = (const float*)d_in[2];
    l0_kernel<<<NPOS, 128>>>(x, w0);

    // Launch 4 (= ncu capture slot): L1 gemm  96 -> 192 (bufA stride 128)
    gemm_mma_kernel<<<dim3(NPOS / 128, 2), 256, GSMEM>>>(
        wHi + WOFF1, wLo + WOFF1, bufA_hi, bufA_lo, 128, 96, 192, 96, 1,
        bufB_hi, bufB_lo, 192, nullptr);

    // L2: 192 -> 384
    gemm_mma_kernel<<<dim3(NPOS / 128, 3), 256, GSMEM>>>(
        wHi + WOFF2, wLo + WOFF2, bufB_hi, bufB_lo, 192, 192, 384, 288, 1,
        bufA_hi, bufA_lo, 384, nullptr);

    // L3: 384 -> 768
    gemm_mma_kernel<<<dim3(NPOS / 128, 6), 256, GSMEM>>>(
        wHi + WOFF3, wLo + WOFF3, bufA_hi, bufA_lo, 384, 384, 768, 672, 1,
        bufB_hi, bufB_lo, 768, nullptr);

    // L4: 768 -> 768 -> final fp32 output [B][768][196]
    gemm_mma_kernel<<<dim3(NPOS / 128, 6), 256, GSMEM>>>(
        wHi + WOFF4, wLo + WOFF4, bufB_hi, bufB_lo, 768, 768, 768, 1440, 0,
        nullptr, nullptr, 0, h_out);

    // sliced copy (independent; last)
    if (front > 0) {
        int n4 = (int)(front / 4);
        copy_sliced_kernel<<<(n4 + 255) / 256, 256>>>(sliced, out_f, n4);
    }
}